// round 6
// baseline (speedup 1.0000x reference)
#include <cuda_runtime.h>
#include <math.h>

// SLIC superpixel k-means: 8 images of 224x224x3, K=100, 10 iterations + final assign.
// Output (float32): [labels (8*224*224)] ++ [mean_img (8*224*224*3)]
//
// R5 changes vs R3:
//  - REVERT TF32 rounding (falsified: reference is full f32)
//  - emulate XLA rounding order: f_sq/csq via explicit rounded mul+add (no fma
//    contraction, matching mul-HLO + reduce-HLO); dot via sequential fma chain
//    in feature order (cublas/Eigen GEMM k-loop)
//  - keep: fixed-point int64 deterministic accumulation, PPT=2 occupancy layout

#define BATCH 8
#define H 224
#define W 224
#define HW (H * W)               // 50176
#define K 100
#define NITER 10
#define TPB 256
#define PPT 2
#define PPB (TPB * PPT)          // 512
#define BLKS_PER_IMG (HW / PPB)  // 98 exactly
#define FIX_SCALE 67108864.0     // 2^26

__device__ float g_centers[BATCH][K][5];
__device__ unsigned long long g_acc[BATCH][K][6];  // 5 fixed-point feat sums + count

__device__ __forceinline__ float slic_ratio() {
    // compactness / S, S = sqrt(H*W/K); double then rounded to f32
    return (float)(10.0 / sqrt((double)HW / (double)K));
}

__device__ __forceinline__ unsigned long long fixp(float v) {
    return (unsigned long long)__double2ll_rn((double)v * FIX_SCALE);
}

// XLA-style sum of squares: each product rounded, then sequential adds (no fma)
__device__ __forceinline__ float sumsq5(float a, float b, float c, float d, float e) {
    float s = __fmul_rn(a, a);
    s = __fadd_rn(s, __fmul_rn(b, b));
    s = __fadd_rn(s, __fmul_rn(c, c));
    s = __fadd_rn(s, __fmul_rn(d, d));
    s = __fadd_rn(s, __fmul_rn(e, e));
    return s;
}

// GEMM-style k-chain: acc = fma(a4,b4, fma(a3,b3, ... fma(a1,b1, a0*b0)))
__device__ __forceinline__ float dot5(float a0, float a1, float a2, float a3, float a4,
                                      float b0, float b1, float b2, float b3, float b4) {
    float s = __fmul_rn(a0, b0);
    s = __fmaf_rn(a1, b1, s);
    s = __fmaf_rn(a2, b2, s);
    s = __fmaf_rn(a3, b3, s);
    s = __fmaf_rn(a4, b4, s);
    return s;
}

// --- init: centers on regular grid, zero accumulators ---
__global__ void slic_init_kernel(const float* __restrict__ img) {
    int b = blockIdx.x;
    int t = threadIdx.x;
    if (t < K) {
        int gi = t / 10, gj = t % 10;
        // floor(((i+0.5)*224)/10) in double — f32 gives 167 instead of 168 at i=7
        int cy = (int)floor(((double)gi + 0.5) * (double)H / 10.0);
        int cx = (int)floor(((double)gj + 0.5) * (double)W / 10.0);
        int p = cy * W + cx;
        const float* px = img + ((size_t)b * HW + p) * 3;
        float ratio = slic_ratio();
        g_centers[b][t][0] = __fmul_rn((float)cy, ratio);
        g_centers[b][t][1] = __fmul_rn((float)cx, ratio);
        g_centers[b][t][2] = px[0];
        g_centers[b][t][3] = px[1];
        g_centers[b][t][4] = px[2];
    }
    unsigned long long* acc = (unsigned long long*)g_acc[b];
    for (int i = t; i < K * 6; i += blockDim.x) acc[i] = 0ULL;
}

// --- assign (+ fixed-point accumulate, or + write final outputs) ---
template <int FINAL>
__global__ __launch_bounds__(TPB, 6) void slic_assign_kernel(
    const float* __restrict__ img, float* __restrict__ out)
{
    __shared__ float4 s_c8[K * 2];               // c0..c4, csq, pad, pad (two float4/center)
    __shared__ unsigned long long s_acc[K * 6];

    const int b = blockIdx.y;
    const int t = threadIdx.x;

    const float* cbase = (const float*)g_centers[b];
    __shared__ float s_tmp[K * 5];
    for (int i = t; i < K * 5; i += TPB) s_tmp[i] = cbase[i];
    if (!FINAL) {
        for (int i = t; i < K * 6; i += TPB) s_acc[i] = 0ULL;
    }
    __syncthreads();
    if (t < K) {
        float c0 = s_tmp[t * 5 + 0], c1 = s_tmp[t * 5 + 1], c2 = s_tmp[t * 5 + 2];
        float c3 = s_tmp[t * 5 + 3], c4 = s_tmp[t * 5 + 4];
        float csq = sumsq5(c0, c1, c2, c3, c4);           // XLA rounding order
        s_c8[t * 2 + 0] = make_float4(c0, c1, c2, c3);
        s_c8[t * 2 + 1] = make_float4(c4, csq, 0.0f, 0.0f);
    }
    __syncthreads();

    const float ratio = slic_ratio();
    const int p0 = blockIdx.x * PPB + t * PPT;   // 2 consecutive pixels, same row (W even)

    // 6 floats = 3x float2, 8B aligned
    const float2* src = (const float2*)(img + ((size_t)b * HW + p0) * 3);
    float2 a0 = src[0], a1 = src[1], a2 = src[2];
    float cr[2] = {a0.x, a1.y};
    float cg[2] = {a0.y, a2.x};
    float cb[2] = {a1.x, a2.y};

    const int y0 = p0 / W;
    const int x0 = p0 - y0 * W;
    const float fy0 = __fmul_rn((float)y0, ratio);
    float fx[2] = {__fmul_rn((float)x0, ratio), __fmul_rn((float)(x0 + 1), ratio)};

    float fsq[2], bd[2];
    int bk[2];
#pragma unroll
    for (int j = 0; j < PPT; j++) {
        fsq[j] = sumsq5(fy0, fx[j], cr[j], cg[j], cb[j]);  // XLA rounding order
        bd[j] = 3.4e38f;
        bk[j] = 0;
    }

    // d = (f_sq + |c|^2) - 2*dot (reference formula); strict '<' = first-index argmin
#pragma unroll 2
    for (int k = 0; k < K; k++) {
        float4 ca = s_c8[k * 2 + 0];
        float4 cv = s_c8[k * 2 + 1];
#pragma unroll
        for (int j = 0; j < PPT; j++) {
            float dot = dot5(fy0, fx[j], cr[j], cg[j], cb[j],
                             ca.x, ca.y, ca.z, ca.w, cv.x);
            float d = __fsub_rn(__fadd_rn(fsq[j], cv.y), __fmul_rn(2.0f, dot));
            if (d < bd[j]) { bd[j] = d; bk[j] = k; }
        }
    }

    if (FINAL) {
        float* mean_out = out + (size_t)BATCH * HW;
#pragma unroll
        for (int j = 0; j < PPT; j++) {
            int p = p0 + j;
            int k = bk[j];
            out[(size_t)b * HW + p] = (float)k;               // labels as f32
            float4 cc = s_c8[k * 2 + 0];
            float c4v = s_c8[k * 2 + 1].x;
            float* m = mean_out + ((size_t)b * HW + p) * 3;
            m[0] = cc.z;
            m[1] = cc.w;
            m[2] = c4v;
        }
    } else {
        // exact, order-independent fixed-point accumulation
        if (bk[0] == bk[1]) {
            unsigned long long* a = &s_acc[bk[0] * 6];
            atomicAdd(&a[0], 2ULL * fixp(fy0));
            atomicAdd(&a[1], fixp(fx[0]) + fixp(fx[1]));
            atomicAdd(&a[2], fixp(cr[0]) + fixp(cr[1]));
            atomicAdd(&a[3], fixp(cg[0]) + fixp(cg[1]));
            atomicAdd(&a[4], fixp(cb[0]) + fixp(cb[1]));
            atomicAdd(&a[5], 2ULL);
        } else {
#pragma unroll
            for (int j = 0; j < PPT; j++) {
                unsigned long long* a = &s_acc[bk[j] * 6];
                atomicAdd(&a[0], fixp(fy0));
                atomicAdd(&a[1], fixp(fx[j]));
                atomicAdd(&a[2], fixp(cr[j]));
                atomicAdd(&a[3], fixp(cg[j]));
                atomicAdd(&a[4], fixp(cb[j]));
                atomicAdd(&a[5], 1ULL);
            }
        }
        __syncthreads();

        unsigned long long* gacc = (unsigned long long*)g_acc[b];
        for (int i = t; i < K * 6; i += TPB) {
            unsigned long long v = s_acc[i];
            if (v) atomicAdd(&gacc[i], v);   // integer: exact & order-independent
        }
    }
}

// --- center update: cluster means; keep old center if empty; re-zero accumulators ---
__global__ void slic_update_kernel() {
    int b = blockIdx.x;
    int t = threadIdx.x;
    if (t < K) {
        unsigned long long cnt_u = g_acc[b][t][5];
        if (cnt_u > 0ULL) {
            float cnt = (float)(long long)cnt_u;
            float den = fmaxf(cnt, 1.0f);
#pragma unroll
            for (int i = 0; i < 5; i++) {
                // exact integer sum -> f32 (one rounding), then IEEE f32 divide like jnp
                float s = (float)((double)(long long)g_acc[b][t][i] * (1.0 / FIX_SCALE));
                g_centers[b][t][i] = __fdiv_rn(s, den);
            }
        }
    }
    __syncthreads();
    unsigned long long* acc = (unsigned long long*)g_acc[b];
    for (int i = t; i < K * 6; i += blockDim.x) acc[i] = 0ULL;
}

extern "C" void kernel_launch(void* const* d_in, const int* in_sizes, int n_in,
                              void* d_out, int out_size)
{
    const float* img = (const float*)d_in[0];
    float* out = (float*)d_out;
    (void)in_sizes; (void)n_in; (void)out_size;

    slic_init_kernel<<<BATCH, 128>>>(img);

    dim3 grid(BLKS_PER_IMG, BATCH);
    for (int it = 0; it < NITER; ++it) {
        slic_assign_kernel<0><<<grid, TPB>>>(img, out);
        slic_update_kernel<<<BATCH, 128>>>();
    }
    slic_assign_kernel<1><<<grid, TPB>>>(img, out);
}

// round 8
// speedup vs baseline: 1.0948x; 1.0948x over previous
#include <cuda_runtime.h>
#include <math.h>

// SLIC superpixel k-means: 8 images of 224x224x3, K=100, 10 iterations + final assign.
// Output (float32): [labels (8*224*224)] ++ [mean_img (8*224*224*3)]
//
// R6 changes vs R5 (numerics byte-identical to R5's passing run):
//  - 32x16 pixel tiles + per-block candidate pruning via exact spatial interval
//    bounds (color term bounded by 3, margin 2.0 >> rounding) -> ~7x less inner work
//  - PPT=4 (4 independent fma chains) to hide the serial rounded-fma latency
//  - center update folded into assign prologue (fixed-point accumulators are exact
//    integers -> every block recomputes bit-identical centers); no update kernels

#define BATCH 8
#define H 224
#define W 224
#define HW (H * W)          // 50176
#define K 100
#define NITER 10
#define TPB 128
#define PPT 4
#define TILE_X 32
#define TILE_Y 16
#define NTX (W / TILE_X)    // 7
#define NTY (H / TILE_Y)    // 14
#define FIX_SCALE 67108864.0  // 2^26
#define MARGIN 2.0f

__device__ float g_cstore[NITER][BATCH][K][5];                // centers used at pass p (fallback chain)
__device__ unsigned long long g_acc[NITER][BATCH][K][6];      // per-pass fixed-point accumulators

__device__ __forceinline__ float slic_ratio() {
    return (float)(10.0 / sqrt((double)HW / (double)K));
}

__device__ __forceinline__ unsigned long long fixp(float v) {
    return (unsigned long long)__double2ll_rn((double)v * FIX_SCALE);
}

// XLA-style sum of squares: each product rounded, then sequential adds (no fma)
__device__ __forceinline__ float sumsq5(float a, float b, float c, float d, float e) {
    float s = __fmul_rn(a, a);
    s = __fadd_rn(s, __fmul_rn(b, b));
    s = __fadd_rn(s, __fmul_rn(c, c));
    s = __fadd_rn(s, __fmul_rn(d, d));
    s = __fadd_rn(s, __fmul_rn(e, e));
    return s;
}

// GEMM-style k-chain: fma(a4,b4, fma(... fma(a1,b1, a0*b0)))
__device__ __forceinline__ float dot5(float a0, float a1, float a2, float a3, float a4,
                                      float b0, float b1, float b2, float b3, float b4) {
    float s = __fmul_rn(a0, b0);
    s = __fmaf_rn(a1, b1, s);
    s = __fmaf_rn(a2, b2, s);
    s = __fmaf_rn(a3, b3, s);
    s = __fmaf_rn(a4, b4, s);
    return s;
}

// --- init: grid centers into g_cstore[0], zero ALL accumulators ---
__global__ void slic_init_kernel(const float* __restrict__ img) {
    int b = blockIdx.x;
    int t = threadIdx.x;
    if (t < K) {
        int gi = t / 10, gj = t % 10;
        int cy = (int)floor(((double)gi + 0.5) * (double)H / 10.0);
        int cx = (int)floor(((double)gj + 0.5) * (double)W / 10.0);
        int p = cy * W + cx;
        const float* px = img + ((size_t)b * HW + p) * 3;
        float ratio = slic_ratio();
        g_cstore[0][b][t][0] = __fmul_rn((float)cy, ratio);
        g_cstore[0][b][t][1] = __fmul_rn((float)cx, ratio);
        g_cstore[0][b][t][2] = px[0];
        g_cstore[0][b][t][3] = px[1];
        g_cstore[0][b][t][4] = px[2];
    }
    for (int it = 0; it < NITER; it++) {
        unsigned long long* acc = (unsigned long long*)g_acc[it][b];
        for (int i = t; i < K * 6; i += blockDim.x) acc[i] = 0ULL;
    }
}

// --- one pass: recompute centers, prune candidates, assign; accumulate or emit ---
__global__ __launch_bounds__(TPB, 8) void slic_pass_kernel(
    const float* __restrict__ img, float* __restrict__ out, int iter)
{
    __shared__ float4 s_c[K * 2];    // all centers: (c0..c3), (c4, csq, -, -)
    __shared__ float4 s_cd[K * 2];   // candidates:  (c0..c3), (c4, csq, k_bits, -)
    __shared__ unsigned long long s_acc[K * 6];
    __shared__ unsigned s_bal[4];
    __shared__ int s_ubi;
    __shared__ int s_ncand;

    const int b = blockIdx.z;
    const int t = threadIdx.x;

    if (t == 0) s_ubi = 0x7f7fffff;  // +FLT_MAX bits (positive floats: int order == float order)
    if (iter < NITER) {
        for (int i = t; i < K * 6; i += TPB) s_acc[i] = 0ULL;
    }

    // ---- centers (bit-identical in every block: pure f(exact integer accumulators)) ----
    if (t < K) {
        float c[5];
        if (iter == 0) {
#pragma unroll
            for (int i = 0; i < 5; i++) c[i] = g_cstore[0][b][t][i];
        } else {
            const unsigned long long* a = g_acc[iter - 1][b][t];
            unsigned long long cnt = a[5];
            if (cnt > 0ULL) {
                float den = fmaxf((float)(long long)cnt, 1.0f);
#pragma unroll
                for (int i = 0; i < 5; i++) {
                    float s = (float)((double)(long long)a[i] * (1.0 / FIX_SCALE));
                    c[i] = __fdiv_rn(s, den);
                }
            } else {
#pragma unroll
                for (int i = 0; i < 5; i++) c[i] = g_cstore[iter - 1][b][t][i];
            }
        }
        float csq = sumsq5(c[0], c[1], c[2], c[3], c[4]);
        s_c[t * 2 + 0] = make_float4(c[0], c[1], c[2], c[3]);
        s_c[t * 2 + 1] = make_float4(c[4], csq, 0.0f, 0.0f);
        // designated block persists this pass's centers (empty-cluster fallback chain)
        if (iter >= 1 && iter < NITER && blockIdx.x == 0 && blockIdx.y == 0) {
#pragma unroll
            for (int i = 0; i < 5; i++) g_cstore[iter][b][t][i] = c[i];
        }
    }
    __syncthreads();

    // ---- candidate pruning: exact interval bounds on the tile's feature box ----
    const float ratio = slic_ratio();
    const int ty0 = blockIdx.y * TILE_Y, tx0 = blockIdx.x * TILE_X;
    const float fy_lo = __fmul_rn((float)ty0, ratio);
    const float fy_hi = __fmul_rn((float)(ty0 + TILE_Y - 1), ratio);
    const float fx_lo = __fmul_rn((float)tx0, ratio);
    const float fx_hi = __fmul_rn((float)(tx0 + TILE_X - 1), ratio);

    float lb = 0.0f;
    if (t < K) {
        float cy = s_c[t * 2].x, cx = s_c[t * 2].y;
        float dy = fmaxf(fmaxf(fy_lo - cy, cy - fy_hi), 0.0f);   // box distance
        float dx = fmaxf(fmaxf(fx_lo - cx, cx - fx_hi), 0.0f);
        lb = dy * dy + dx * dx;                                   // spatial lower bound
        float Dy = fmaxf(cy - fy_lo, fy_hi - cy);                 // max |c - endpoint|
        float Dx = fmaxf(cx - fx_lo, fx_hi - cx);
        float ub = Dy * Dy + Dx * Dx + 3.0f;                      // + max color dist^2
        atomicMin(&s_ubi, __float_as_int(ub));
    }
    __syncthreads();
    const float minub = __int_as_float(s_ubi);

    bool flag = (t < K) && (lb <= minub + MARGIN);
    unsigned bal = __ballot_sync(0xffffffffu, flag);
    int wrp = t >> 5;
    if ((t & 31) == 0) s_bal[wrp] = bal;
    __syncthreads();
    if (flag) {
        int pos = __popc(bal & ((1u << (t & 31)) - 1u));
#pragma unroll
        for (int w = 0; w < 4; w++)
            if (w < wrp) pos += __popc(s_bal[w]);
        s_cd[pos * 2 + 0] = s_c[t * 2 + 0];
        float4 v = s_c[t * 2 + 1];
        v.z = __int_as_float(t);                                  // original k
        s_cd[pos * 2 + 1] = v;
    }
    if (t == 0)
        s_ncand = __popc(s_bal[0]) + __popc(s_bal[1]) + __popc(s_bal[2]) + __popc(s_bal[3]);
    __syncthreads();
    const int ncand = s_ncand;

    // ---- load 4 consecutive pixels (one row), 3x float4 coalesced ----
    const int r = t >> 3;                       // tile row 0..15
    const int y = ty0 + r;
    const int x0 = tx0 + (t & 7) * PPT;
    const float4* p4 = (const float4*)(img + ((size_t)b * HW + (size_t)y * W + x0) * 3);
    float4 q0 = p4[0], q1 = p4[1], q2 = p4[2];
    float cr[4] = {q0.x, q0.w, q1.z, q2.y};
    float cg[4] = {q0.y, q1.x, q1.w, q2.z};
    float cb[4] = {q0.z, q1.y, q2.x, q2.w};

    const float fy = __fmul_rn((float)y, ratio);
    float fx[4], fsq[4], bd[4];
    int bk[4];
#pragma unroll
    for (int j = 0; j < PPT; j++) {
        fx[j] = __fmul_rn((float)(x0 + j), ratio);
        fsq[j] = sumsq5(fy, fx[j], cr[j], cg[j], cb[j]);          // XLA rounding order
        bd[j] = 3.4e38f;
        bk[j] = 0;
    }

    // ---- argmin over candidates (ascending k; strict '<' = first-index tie-break) ----
    for (int i = 0; i < ncand; i++) {
        float4 ca = s_cd[i * 2 + 0];
        float4 cv = s_cd[i * 2 + 1];
        int k = __float_as_int(cv.z);
#pragma unroll
        for (int j = 0; j < PPT; j++) {
            float dot = dot5(fy, fx[j], cr[j], cg[j], cb[j],
                             ca.x, ca.y, ca.z, ca.w, cv.x);
            float d = __fsub_rn(__fadd_rn(fsq[j], cv.y), __fmul_rn(2.0f, dot));
            if (d < bd[j]) { bd[j] = d; bk[j] = k; }
        }
    }

    if (iter == NITER) {
        // ---- final outputs: labels (as f32) + superpixel-mean image ----
        float* lbl = out + (size_t)b * HW + (size_t)y * W + x0;
        *(float4*)lbl = make_float4((float)bk[0], (float)bk[1], (float)bk[2], (float)bk[3]);
        float* m = out + (size_t)BATCH * HW + ((size_t)b * HW + (size_t)y * W + x0) * 3;
#pragma unroll
        for (int j = 0; j < PPT; j++) {
            int k = bk[j];
            float4 cc = s_c[k * 2 + 0];
            m[j * 3 + 0] = cc.z;
            m[j * 3 + 1] = cc.w;
            m[j * 3 + 2] = s_c[k * 2 + 1].x;
        }
    } else {
        // ---- exact fixed-point accumulation, run-length compressed ----
        int cur = bk[0];
        unsigned long long a0 = fixp(fy), a1 = fixp(fx[0]);
        unsigned long long a2 = fixp(cr[0]), a3 = fixp(cg[0]), a4 = fixp(cb[0]);
        unsigned long long an = 1ULL;
        const unsigned long long fyq = a0;
#pragma unroll
        for (int j = 1; j < PPT; j++) {
            if (bk[j] == cur) {
                a0 += fyq; a1 += fixp(fx[j]);
                a2 += fixp(cr[j]); a3 += fixp(cg[j]); a4 += fixp(cb[j]);
                an += 1ULL;
            } else {
                unsigned long long* a = &s_acc[cur * 6];
                atomicAdd(&a[0], a0); atomicAdd(&a[1], a1); atomicAdd(&a[2], a2);
                atomicAdd(&a[3], a3); atomicAdd(&a[4], a4); atomicAdd(&a[5], an);
                cur = bk[j];
                a0 = fyq; a1 = fixp(fx[j]);
                a2 = fixp(cr[j]); a3 = fixp(cg[j]); a4 = fixp(cb[j]);
                an = 1ULL;
            }
        }
        {
            unsigned long long* a = &s_acc[cur * 6];
            atomicAdd(&a[0], a0); atomicAdd(&a[1], a1); atomicAdd(&a[2], a2);
            atomicAdd(&a[3], a3); atomicAdd(&a[4], a4); atomicAdd(&a[5], an);
        }
        __syncthreads();
        unsigned long long* gacc = (unsigned long long*)g_acc[iter][b];
        for (int i = t; i < K * 6; i += TPB) {
            unsigned long long v = s_acc[i];
            if (v) atomicAdd(&gacc[i], v);    // integer: exact & order-independent
        }
    }
}

extern "C" void kernel_launch(void* const* d_in, const int* in_sizes, int n_in,
                              void* d_out, int out_size)
{
    const float* img = (const float*)d_in[0];
    float* out = (float*)d_out;
    (void)in_sizes; (void)n_in; (void)out_size;

    slic_init_kernel<<<BATCH, 256>>>(img);

    dim3 grid(NTX, NTY, BATCH);
    for (int p = 0; p <= NITER; ++p) {
        slic_pass_kernel<<<grid, TPB>>>(img, out, p);
    }
}

// round 9
// speedup vs baseline: 1.4084x; 1.2864x over previous
#include <cuda_runtime.h>
#include <math.h>

// SLIC superpixel k-means: 8 images of 224x224x3, K=100, 10 iterations + final assign.
// Output (float32): [labels (8*224*224)] ++ [mean_img (8*224*224*3)]
//
// R8 changes vs R6 (outputs bit-identical):
//  - FP64 eliminated from hot path. Power-of-2 scaling is exact in binary FP:
//      fixp:   __float2ll_rn(v * 2^26f)            == __double2ll_rn((double)v * 2^26)
//      center: __ll2float_rn(sum) * 2^-26f (exact) == (float)((double)sum * 2^-26)
//    (sm_103a FP64 pipe is ~18cyc rt/SM — it was the hidden 40us/pass floor)
//  - ratio (f64 sqrt) computed once in init into __device__ float; passes load it

#define BATCH 8
#define H 224
#define W 224
#define HW (H * W)          // 50176
#define K 100
#define NITER 10
#define TPB 128
#define PPT 4
#define TILE_X 32
#define TILE_Y 16
#define NTX (W / TILE_X)    // 7
#define NTY (H / TILE_Y)    // 14
#define FIX_SCALE_F 67108864.0f   // 2^26 (exact in f32)
#define INV_FIX_F 1.4901161193847656e-8f  // 2^-26 (exact in f32)
#define MARGIN 2.0f

__device__ float g_ratio;
__device__ float g_cstore[NITER][BATCH][K][5];            // centers used at pass p (fallback chain)
__device__ unsigned long long g_acc[NITER][BATCH][K][6];  // per-pass fixed-point accumulators

// v >= 0; v*2^26 is an exact exponent shift in f32, then one rn-round to integer.
// Bit-identical to the previous f64 path.
__device__ __forceinline__ unsigned long long fixp(float v) {
    return (unsigned long long)__float2ll_rn(v * FIX_SCALE_F);
}

// XLA-style sum of squares: each product rounded, then sequential adds (no fma)
__device__ __forceinline__ float sumsq5(float a, float b, float c, float d, float e) {
    float s = __fmul_rn(a, a);
    s = __fadd_rn(s, __fmul_rn(b, b));
    s = __fadd_rn(s, __fmul_rn(c, c));
    s = __fadd_rn(s, __fmul_rn(d, d));
    s = __fadd_rn(s, __fmul_rn(e, e));
    return s;
}

// GEMM-style k-chain: fma(a4,b4, fma(... fma(a1,b1, a0*b0)))
__device__ __forceinline__ float dot5(float a0, float a1, float a2, float a3, float a4,
                                      float b0, float b1, float b2, float b3, float b4) {
    float s = __fmul_rn(a0, b0);
    s = __fmaf_rn(a1, b1, s);
    s = __fmaf_rn(a2, b2, s);
    s = __fmaf_rn(a3, b3, s);
    s = __fmaf_rn(a4, b4, s);
    return s;
}

// --- init: ratio, grid centers into g_cstore[0], zero ALL accumulators ---
__global__ void slic_init_kernel(const float* __restrict__ img) {
    int b = blockIdx.x;
    int t = threadIdx.x;
    // f64 allowed here (runs once, off the hot path)
    float ratio = (float)(10.0 / sqrt((double)HW / (double)K));
    if (b == 0 && t == 0) g_ratio = ratio;
    if (t < K) {
        int gi = t / 10, gj = t % 10;
        int cy = (int)floor(((double)gi + 0.5) * (double)H / 10.0);
        int cx = (int)floor(((double)gj + 0.5) * (double)W / 10.0);
        int p = cy * W + cx;
        const float* px = img + ((size_t)b * HW + p) * 3;
        g_cstore[0][b][t][0] = __fmul_rn((float)cy, ratio);
        g_cstore[0][b][t][1] = __fmul_rn((float)cx, ratio);
        g_cstore[0][b][t][2] = px[0];
        g_cstore[0][b][t][3] = px[1];
        g_cstore[0][b][t][4] = px[2];
    }
    for (int it = 0; it < NITER; it++) {
        unsigned long long* acc = (unsigned long long*)g_acc[it][b];
        for (int i = t; i < K * 6; i += blockDim.x) acc[i] = 0ULL;
    }
}

// --- one pass: recompute centers, prune candidates, assign; accumulate or emit ---
__global__ __launch_bounds__(TPB, 8) void slic_pass_kernel(
    const float* __restrict__ img, float* __restrict__ out, int iter)
{
    __shared__ float4 s_c[K * 2];    // all centers: (c0..c3), (c4, csq, -, -)
    __shared__ float4 s_cd[K * 2];   // candidates:  (c0..c3), (c4, csq, k_bits, -)
    __shared__ unsigned long long s_acc[K * 6];
    __shared__ unsigned s_bal[4];
    __shared__ int s_ubi;
    __shared__ int s_ncand;

    const int b = blockIdx.z;
    const int t = threadIdx.x;

    if (t == 0) s_ubi = 0x7f7fffff;  // +FLT_MAX bits (positive floats: int order == float order)
    if (iter < NITER) {
        for (int i = t; i < K * 6; i += TPB) s_acc[i] = 0ULL;
    }

    // ---- centers (bit-identical in every block: pure f(exact integer accumulators)) ----
    if (t < K) {
        float c[5];
        if (iter == 0) {
#pragma unroll
            for (int i = 0; i < 5; i++) c[i] = g_cstore[0][b][t][i];
        } else {
            const unsigned long long* a = g_acc[iter - 1][b][t];
            unsigned long long cnt = a[5];
            if (cnt > 0ULL) {
                float den = fmaxf(__ll2float_rn((long long)cnt), 1.0f);
#pragma unroll
                for (int i = 0; i < 5; i++) {
                    // s64 -> f32 (one rn-round) then exact 2^-26 shift:
                    // bit-identical to (float)((double)sum * 2^-26)
                    float s = __ll2float_rn((long long)a[i]) * INV_FIX_F;
                    c[i] = __fdiv_rn(s, den);
                }
            } else {
#pragma unroll
                for (int i = 0; i < 5; i++) c[i] = g_cstore[iter - 1][b][t][i];
            }
        }
        float csq = sumsq5(c[0], c[1], c[2], c[3], c[4]);
        s_c[t * 2 + 0] = make_float4(c[0], c[1], c[2], c[3]);
        s_c[t * 2 + 1] = make_float4(c[4], csq, 0.0f, 0.0f);
        // designated block persists this pass's centers (empty-cluster fallback chain)
        if (iter >= 1 && iter < NITER && blockIdx.x == 0 && blockIdx.y == 0) {
#pragma unroll
            for (int i = 0; i < 5; i++) g_cstore[iter][b][t][i] = c[i];
        }
    }
    const float ratio = g_ratio;
    __syncthreads();

    // ---- candidate pruning: exact interval bounds on the tile's feature box ----
    const int ty0 = blockIdx.y * TILE_Y, tx0 = blockIdx.x * TILE_X;
    const float fy_lo = __fmul_rn((float)ty0, ratio);
    const float fy_hi = __fmul_rn((float)(ty0 + TILE_Y - 1), ratio);
    const float fx_lo = __fmul_rn((float)tx0, ratio);
    const float fx_hi = __fmul_rn((float)(tx0 + TILE_X - 1), ratio);

    float lb = 0.0f;
    if (t < K) {
        float cy = s_c[t * 2].x, cx = s_c[t * 2].y;
        float dy = fmaxf(fmaxf(fy_lo - cy, cy - fy_hi), 0.0f);   // box distance
        float dx = fmaxf(fmaxf(fx_lo - cx, cx - fx_hi), 0.0f);
        lb = dy * dy + dx * dx;                                   // spatial lower bound
        float Dy = fmaxf(cy - fy_lo, fy_hi - cy);                 // max |c - endpoint|
        float Dx = fmaxf(cx - fx_lo, fx_hi - cx);
        float ub = Dy * Dy + Dx * Dx + 3.0f;                      // + max color dist^2
        atomicMin(&s_ubi, __float_as_int(ub));
    }
    __syncthreads();
    const float minub = __int_as_float(s_ubi);

    bool flag = (t < K) && (lb <= minub + MARGIN);
    unsigned bal = __ballot_sync(0xffffffffu, flag);
    int wrp = t >> 5;
    if ((t & 31) == 0) s_bal[wrp] = bal;
    __syncthreads();
    if (flag) {
        int pos = __popc(bal & ((1u << (t & 31)) - 1u));
#pragma unroll
        for (int w = 0; w < 4; w++)
            if (w < wrp) pos += __popc(s_bal[w]);
        s_cd[pos * 2 + 0] = s_c[t * 2 + 0];
        float4 v = s_c[t * 2 + 1];
        v.z = __int_as_float(t);                                  // original k
        s_cd[pos * 2 + 1] = v;
    }
    if (t == 0)
        s_ncand = __popc(s_bal[0]) + __popc(s_bal[1]) + __popc(s_bal[2]) + __popc(s_bal[3]);
    __syncthreads();
    const int ncand = s_ncand;

    // ---- load 4 consecutive pixels (one row), 3x float4 coalesced ----
    const int r = t >> 3;                       // tile row 0..15
    const int y = ty0 + r;
    const int x0 = tx0 + (t & 7) * PPT;
    const float4* p4 = (const float4*)(img + ((size_t)b * HW + (size_t)y * W + x0) * 3);
    float4 q0 = p4[0], q1 = p4[1], q2 = p4[2];
    float cr[4] = {q0.x, q0.w, q1.z, q2.y};
    float cg[4] = {q0.y, q1.x, q1.w, q2.z};
    float cb[4] = {q0.z, q1.y, q2.x, q2.w};

    const float fy = __fmul_rn((float)y, ratio);
    float fx[4], fsq[4], bd[4];
    int bk[4];
#pragma unroll
    for (int j = 0; j < PPT; j++) {
        fx[j] = __fmul_rn((float)(x0 + j), ratio);
        fsq[j] = sumsq5(fy, fx[j], cr[j], cg[j], cb[j]);          // XLA rounding order
        bd[j] = 3.4e38f;
        bk[j] = 0;
    }

    // ---- argmin over candidates (ascending k; strict '<' = first-index tie-break) ----
    for (int i = 0; i < ncand; i++) {
        float4 ca = s_cd[i * 2 + 0];
        float4 cv = s_cd[i * 2 + 1];
        int k = __float_as_int(cv.z);
#pragma unroll
        for (int j = 0; j < PPT; j++) {
            float dot = dot5(fy, fx[j], cr[j], cg[j], cb[j],
                             ca.x, ca.y, ca.z, ca.w, cv.x);
            float d = __fsub_rn(__fadd_rn(fsq[j], cv.y), __fmul_rn(2.0f, dot));
            if (d < bd[j]) { bd[j] = d; bk[j] = k; }
        }
    }

    if (iter == NITER) {
        // ---- final outputs: labels (as f32) + superpixel-mean image ----
        float* lbl = out + (size_t)b * HW + (size_t)y * W + x0;
        *(float4*)lbl = make_float4((float)bk[0], (float)bk[1], (float)bk[2], (float)bk[3]);
        float* m = out + (size_t)BATCH * HW + ((size_t)b * HW + (size_t)y * W + x0) * 3;
#pragma unroll
        for (int j = 0; j < PPT; j++) {
            int k = bk[j];
            float4 cc = s_c[k * 2 + 0];
            m[j * 3 + 0] = cc.z;
            m[j * 3 + 1] = cc.w;
            m[j * 3 + 2] = s_c[k * 2 + 1].x;
        }
    } else {
        // ---- exact fixed-point accumulation, run-length compressed (all f32/int) ----
        int cur = bk[0];
        unsigned long long a0 = fixp(fy), a1 = fixp(fx[0]);
        unsigned long long a2 = fixp(cr[0]), a3 = fixp(cg[0]), a4 = fixp(cb[0]);
        unsigned long long an = 1ULL;
        const unsigned long long fyq = a0;
#pragma unroll
        for (int j = 1; j < PPT; j++) {
            if (bk[j] == cur) {
                a0 += fyq; a1 += fixp(fx[j]);
                a2 += fixp(cr[j]); a3 += fixp(cg[j]); a4 += fixp(cb[j]);
                an += 1ULL;
            } else {
                unsigned long long* a = &s_acc[cur * 6];
                atomicAdd(&a[0], a0); atomicAdd(&a[1], a1); atomicAdd(&a[2], a2);
                atomicAdd(&a[3], a3); atomicAdd(&a[4], a4); atomicAdd(&a[5], an);
                cur = bk[j];
                a0 = fyq; a1 = fixp(fx[j]);
                a2 = fixp(cr[j]); a3 = fixp(cg[j]); a4 = fixp(cb[j]);
                an = 1ULL;
            }
        }
        {
            unsigned long long* a = &s_acc[cur * 6];
            atomicAdd(&a[0], a0); atomicAdd(&a[1], a1); atomicAdd(&a[2], a2);
            atomicAdd(&a[3], a3); atomicAdd(&a[4], a4); atomicAdd(&a[5], an);
        }
        __syncthreads();
        unsigned long long* gacc = (unsigned long long*)g_acc[iter][b];
        for (int i = t; i < K * 6; i += TPB) {
            unsigned long long v = s_acc[i];
            if (v) atomicAdd(&gacc[i], v);    // integer: exact & order-independent
        }
    }
}

extern "C" void kernel_launch(void* const* d_in, const int* in_sizes, int n_in,
                              void* d_out, int out_size)
{
    const float* img = (const float*)d_in[0];
    float* out = (float*)d_out;
    (void)in_sizes; (void)n_in; (void)out_size;

    slic_init_kernel<<<BATCH, 256>>>(img);

    dim3 grid(NTX, NTY, BATCH);
    for (int p = 0; p <= NITER; ++p) {
        slic_pass_kernel<<<grid, TPB>>>(img, out, p);
    }
}